// round 3
// baseline (speedup 1.0000x reference)
#include <cuda_runtime.h>
#include <cuda_bf16.h>
#include <cstdint>

#define NN 8192
#define EE 131072
#define MUL 128
#define AA 10
#define RB 8
#define DEF 264       // RB + 2*MUL
#define HID 64

#define R128 0.08838834764831845f
#define R10  0.31622776601683794f
#define RS264 0.06154574548966637f
#define INV3 0.5773502691896258f

// ---------------- scratch (device globals; no allocation allowed) ----------------
__device__ float  g_us[NN * 128];        // up-scalar
__device__ float  g_uv[NN * 384];        // up-vector [n][u][c]
__device__ float  g_src[NN * 128];
__device__ float  g_tgt[NN * 128];
__device__ float  g_tpw[(size_t)EE * 512];  // edge MLP output (268MB)
__device__ float4 g_msg4[NN * 256];      // [n][u] = (s, v0, v1, v2)
__device__ float  g_density[NN];

__device__ __forceinline__ float silu_f(float x) {
    return x / (1.0f + __expf(-x));
}

__device__ __forceinline__ void red4(float4* p, float a, float b, float c, float d) {
    asm volatile("red.global.add.v4.f32 [%0], {%1,%2,%3,%4};"
                 :: "l"(p), "f"(a), "f"(b), "f"(c), "f"(d) : "memory");
}

// ---------------- K0: zero accumulators ----------------
__global__ void k_zero() {
    int i = blockIdx.x * blockDim.x + threadIdx.x;
    if (i < NN * 256) g_msg4[i] = make_float4(0.f, 0.f, 0.f, 0.f);
    if (i < NN) g_density[i] = 0.f;
}

// ---------------- K1: node pre (us, uv, src_e, tgt_e, sc) ----------------
// 16 nodes per block, 256 threads
__global__ void k_node_pre(const float* __restrict__ na, const float* __restrict__ nf,
                           const float* __restrict__ Wss, const float* __restrict__ Wsv,
                           const float* __restrict__ Wus, const float* __restrict__ Wuv,
                           const float* __restrict__ Wsrc, const float* __restrict__ Wtgt,
                           float* __restrict__ out_sc) {
    __shared__ float s_s[16][128];
    __shared__ float s_v[16][384];
    __shared__ float s_a[16][10];
    int nb = blockIdx.x * 16;
    int tid = threadIdx.x;

    for (int idx = tid; idx < 16 * 512; idx += 256) {
        int nn = idx >> 9, j = idx & 511;
        float val = nf[(nb + nn) * 512 + j];
        if (j < 128) s_s[nn][j] = val;
        else         s_v[nn][j - 128] = val;
    }
    for (int idx = tid; idx < 160; idx += 256) {
        int nn = idx / 10, j = idx - nn * 10;
        s_a[nn][j] = na[(nb + nn) * 10 + j];
    }
    __syncthreads();

    // scalar part: us, sc[:128], src_e, tgt_e   (16*128 items)
    for (int it = tid; it < 2048; it += 256) {
        int nn = it >> 7, w = it & 127;
        float a_up = 0.f, a_sk = 0.f, a_src = 0.f, a_tgt = 0.f;
        #pragma unroll 4
        for (int u = 0; u < 128; u++) {
            float x = s_s[nn][u];
            a_up += x * Wus[u * 128 + w];
            a_sk += x * Wss[u * 128 + w];
        }
        #pragma unroll
        for (int u = 0; u < 10; u++) {
            float x = s_a[nn][u];
            a_src += x * Wsrc[u * 128 + w];
            a_tgt += x * Wtgt[u * 128 + w];
        }
        int n = nb + nn;
        g_us[n * 128 + w]  = a_up * R128;
        g_src[n * 128 + w] = a_src * R10;
        g_tgt[n * 128 + w] = a_tgt * R10;
        out_sc[(size_t)n * 512 + w] = a_sk * R128;
    }
    // vector part: uv, sc[128:]   (16*128*3 items)
    for (int it = tid; it < 6144; it += 256) {
        int nn = it / 384; int r = it - nn * 384;
        int w = r / 3, c = r - 3 * w;
        float a_up = 0.f, a_sk = 0.f;
        #pragma unroll 4
        for (int u = 0; u < 128; u++) {
            float x = s_v[nn][u * 3 + c];
            a_up += x * Wuv[u * 128 + w];
            a_sk += x * Wsv[u * 128 + w];
        }
        int n = nb + nn;
        g_uv[n * 384 + r] = a_up * R128;
        out_sc[(size_t)n * 512 + 128 + r] = a_sk * R128;
    }
}

// ---------------- K2: edge MLP (264->64->64->64->512 and density head) ----------------
// 64 edges per block, 256 threads, dynamic smem
#define K2_EF_STRIDE 265
#define K2_SMEM_FLOATS (64 * K2_EF_STRIDE + 264 * 64 + 64 * 65 + 64 * 65)
__global__ void k_edge_mlp(const float* __restrict__ ef_in, const int* __restrict__ ei,
                           const float* __restrict__ Wr0, const float* __restrict__ Wr1,
                           const float* __restrict__ Wr2, const float* __restrict__ Wr3,
                           const float* __restrict__ Wd0, const float* __restrict__ Wd1) {
    extern __shared__ float sm[];
    float* ef = sm;                       // 64 * 265
    float* Wb = ef + 64 * K2_EF_STRIDE;   // up to 264*64
    float* Ha = Wb + 264 * 64;            // 64 * 65
    float* Hb = Ha + 64 * 65;             // 64 * 65
    __shared__ int s_snd[64], s_rcv[64];

    int eb = blockIdx.x * 64;
    int tid = threadIdx.x;
    if (tid < 64) { s_snd[tid] = ei[eb + tid]; s_rcv[tid] = ei[EE + eb + tid]; }
    __syncthreads();

    // gather ef = [edge_feats(8) | src_e[snd](128) | tgt_e[rcv](128)]
    for (int idx = tid; idx < 64 * 264; idx += 256) {
        int e = idx / 264, i = idx - e * 264;
        float v;
        if (i < 8)         v = ef_in[(eb + e) * 8 + i];
        else if (i < 136)  v = g_src[s_snd[e] * 128 + (i - 8)];
        else               v = g_tgt[s_rcv[e] * 128 + (i - 136)];
        ef[e * K2_EF_STRIDE + i] = v;
    }
    for (int idx = tid; idx < 264 * 64; idx += 256) Wb[idx] = Wr0[idx];
    __syncthreads();

    int og = tid & 15, eg = tid >> 4;
    int e0 = eg * 4, o0 = og * 4;

    // layer 0 (r-path): ef @ Wr0 -> Ha
    {
        float acc[16];
        #pragma unroll
        for (int k = 0; k < 16; k++) acc[k] = 0.f;
        for (int i = 0; i < 264; i++) {
            float x0 = ef[(e0 + 0) * K2_EF_STRIDE + i];
            float x1 = ef[(e0 + 1) * K2_EF_STRIDE + i];
            float x2 = ef[(e0 + 2) * K2_EF_STRIDE + i];
            float x3 = ef[(e0 + 3) * K2_EF_STRIDE + i];
            float4 w = *(const float4*)&Wb[i * 64 + o0];
            acc[0]  += x0 * w.x; acc[1]  += x0 * w.y; acc[2]  += x0 * w.z; acc[3]  += x0 * w.w;
            acc[4]  += x1 * w.x; acc[5]  += x1 * w.y; acc[6]  += x1 * w.z; acc[7]  += x1 * w.w;
            acc[8]  += x2 * w.x; acc[9]  += x2 * w.y; acc[10] += x2 * w.z; acc[11] += x2 * w.w;
            acc[12] += x3 * w.x; acc[13] += x3 * w.y; acc[14] += x3 * w.z; acc[15] += x3 * w.w;
        }
        #pragma unroll
        for (int k = 0; k < 4; k++)
            #pragma unroll
            for (int j = 0; j < 4; j++)
                Ha[(e0 + k) * 65 + o0 + j] = silu_f(acc[k * 4 + j] * RS264);
    }
    __syncthreads();
    for (int idx = tid; idx < 264 * 64; idx += 256) Wb[idx] = Wd0[idx];
    __syncthreads();

    // layer 0 (d-path): ef @ Wd0 -> Hb
    {
        float acc[16];
        #pragma unroll
        for (int k = 0; k < 16; k++) acc[k] = 0.f;
        for (int i = 0; i < 264; i++) {
            float x0 = ef[(e0 + 0) * K2_EF_STRIDE + i];
            float x1 = ef[(e0 + 1) * K2_EF_STRIDE + i];
            float x2 = ef[(e0 + 2) * K2_EF_STRIDE + i];
            float x3 = ef[(e0 + 3) * K2_EF_STRIDE + i];
            float4 w = *(const float4*)&Wb[i * 64 + o0];
            acc[0]  += x0 * w.x; acc[1]  += x0 * w.y; acc[2]  += x0 * w.z; acc[3]  += x0 * w.w;
            acc[4]  += x1 * w.x; acc[5]  += x1 * w.y; acc[6]  += x1 * w.z; acc[7]  += x1 * w.w;
            acc[8]  += x2 * w.x; acc[9]  += x2 * w.y; acc[10] += x2 * w.z; acc[11] += x2 * w.w;
            acc[12] += x3 * w.x; acc[13] += x3 * w.y; acc[14] += x3 * w.z; acc[15] += x3 * w.w;
        }
        #pragma unroll
        for (int k = 0; k < 4; k++)
            #pragma unroll
            for (int j = 0; j < 4; j++)
                Hb[(e0 + k) * 65 + o0 + j] = silu_f(acc[k * 4 + j] * RS264);
    }
    __syncthreads();

    // density head: tanh((Hb @ Wd1 / 8)^2), atomic into density[rcv]
    if (tid < 64) {
        float a = 0.f;
        #pragma unroll 8
        for (int o = 0; o < 64; o++) a += Hb[tid * 65 + o] * Wd1[o];
        a *= 0.125f;
        float ed = tanhf(a * a);
        atomicAdd(&g_density[s_rcv[tid]], ed);
    }
    // load Wr1 (Wb free now)
    for (int idx = tid; idx < 64 * 64; idx += 256) Wb[idx] = Wr1[idx];
    __syncthreads();

    // layer 1: Ha @ Wr1 -> Hb
    {
        float acc[16];
        #pragma unroll
        for (int k = 0; k < 16; k++) acc[k] = 0.f;
        for (int i = 0; i < 64; i++) {
            float x0 = Ha[(e0 + 0) * 65 + i];
            float x1 = Ha[(e0 + 1) * 65 + i];
            float x2 = Ha[(e0 + 2) * 65 + i];
            float x3 = Ha[(e0 + 3) * 65 + i];
            float4 w = *(const float4*)&Wb[i * 64 + o0];
            acc[0]  += x0 * w.x; acc[1]  += x0 * w.y; acc[2]  += x0 * w.z; acc[3]  += x0 * w.w;
            acc[4]  += x1 * w.x; acc[5]  += x1 * w.y; acc[6]  += x1 * w.z; acc[7]  += x1 * w.w;
            acc[8]  += x2 * w.x; acc[9]  += x2 * w.y; acc[10] += x2 * w.z; acc[11] += x2 * w.w;
            acc[12] += x3 * w.x; acc[13] += x3 * w.y; acc[14] += x3 * w.z; acc[15] += x3 * w.w;
        }
        #pragma unroll
        for (int k = 0; k < 4; k++)
            #pragma unroll
            for (int j = 0; j < 4; j++)
                Hb[(e0 + k) * 65 + o0 + j] = silu_f(acc[k * 4 + j] * 0.125f);
    }
    __syncthreads();
    for (int idx = tid; idx < 64 * 64; idx += 256) Wb[idx] = Wr2[idx];
    __syncthreads();

    // layer 2: Hb @ Wr2 -> Ha
    {
        float acc[16];
        #pragma unroll
        for (int k = 0; k < 16; k++) acc[k] = 0.f;
        for (int i = 0; i < 64; i++) {
            float x0 = Hb[(e0 + 0) * 65 + i];
            float x1 = Hb[(e0 + 1) * 65 + i];
            float x2 = Hb[(e0 + 2) * 65 + i];
            float x3 = Hb[(e0 + 3) * 65 + i];
            float4 w = *(const float4*)&Wb[i * 64 + o0];
            acc[0]  += x0 * w.x; acc[1]  += x0 * w.y; acc[2]  += x0 * w.z; acc[3]  += x0 * w.w;
            acc[4]  += x1 * w.x; acc[5]  += x1 * w.y; acc[6]  += x1 * w.z; acc[7]  += x1 * w.w;
            acc[8]  += x2 * w.x; acc[9]  += x2 * w.y; acc[10] += x2 * w.z; acc[11] += x2 * w.w;
            acc[12] += x3 * w.x; acc[13] += x3 * w.y; acc[14] += x3 * w.z; acc[15] += x3 * w.w;
        }
        __syncthreads();   // before we overwrite Ha (everyone done reading Hb? Ha was input to nothing now)
        #pragma unroll
        for (int k = 0; k < 4; k++)
            #pragma unroll
            for (int j = 0; j < 4; j++)
                Ha[(e0 + k) * 65 + o0 + j] = silu_f(acc[k * 4 + j] * 0.125f);
    }
    __syncthreads();

    // layer 3: Ha @ Wr3 (64x512) in 4 chunks of 128 cols -> g_tpw (no activation)
    for (int chunk = 0; chunk < 4; chunk++) {
        for (int idx = tid; idx < 64 * 128; idx += 256) {
            int i = idx >> 7, j = idx & 127;
            Wb[idx] = Wr3[i * 512 + chunk * 128 + j];
        }
        __syncthreads();
        float acc[4][8];
        #pragma unroll
        for (int k = 0; k < 4; k++)
            #pragma unroll
            for (int j = 0; j < 8; j++) acc[k][j] = 0.f;
        int c0 = og * 8;
        for (int i = 0; i < 64; i++) {
            float x0 = Ha[(e0 + 0) * 65 + i];
            float x1 = Ha[(e0 + 1) * 65 + i];
            float x2 = Ha[(e0 + 2) * 65 + i];
            float x3 = Ha[(e0 + 3) * 65 + i];
            float4 wa = *(const float4*)&Wb[i * 128 + c0];
            float4 wb2 = *(const float4*)&Wb[i * 128 + c0 + 4];
            float w[8] = {wa.x, wa.y, wa.z, wa.w, wb2.x, wb2.y, wb2.z, wb2.w};
            #pragma unroll
            for (int j = 0; j < 8; j++) {
                acc[0][j] += x0 * w[j];
                acc[1][j] += x1 * w[j];
                acc[2][j] += x2 * w[j];
                acc[3][j] += x3 * w[j];
            }
        }
        #pragma unroll
        for (int k = 0; k < 4; k++)
            #pragma unroll
            for (int j = 0; j < 8; j++)
                g_tpw[(size_t)(eb + e0 + k) * 512 + chunk * 128 + c0 + j] = acc[k][j] * 0.125f;
        __syncthreads();
    }
}

// ---------------- K3: messages + vectorized scatter-add ----------------
// one warp per edge, 8 edges per block
__global__ void k_message(const float* __restrict__ edge_attrs, const int* __restrict__ ei) {
    int warp = (blockIdx.x * blockDim.x + threadIdx.x) >> 5;
    int lane = threadIdx.x & 31;
    int e = warp;
    int snd = ei[e], rcv = ei[EE + e];
    float y0  = edge_attrs[e * 4 + 0];
    float y1x = edge_attrs[e * 4 + 1];
    float y1y = edge_attrs[e * 4 + 2];
    float y1z = edge_attrs[e * 4 + 3];
    const float* tp = g_tpw + (size_t)e * 512;
    const float* xs = g_us + (size_t)snd * 128;
    const float* xv = g_uv + (size_t)snd * 384;
    float4* mbase = g_msg4 + (size_t)rcv * 256;

    #pragma unroll
    for (int k = 0; k < 4; k++) {
        int u = lane + k * 32;
        float w1 = tp[u], w2 = tp[128 + u], w3 = tp[256 + u], w4 = tp[384 + u];
        float xsu = xs[u];
        // low half: (m0a, m1a)
        float a = w1 * xsu * y0;
        float sx = w2 * xsu * INV3;
        red4(mbase + u, a, sx * y1x, sx * y1y, sx * y1z);
        // high half: (m0b, m1b)
        float vx = xv[u * 3 + 0], vy = xv[u * 3 + 1], vz = xv[u * 3 + 2];
        float dot = vx * y1x + vy * y1y + vz * y1z;
        float a2 = w4 * dot * INV3;
        float s3 = w3 * y0 * INV3;
        red4(mbase + 128 + u, a2, s3 * vx, s3 * vy, s3 * vz);
    }
}

// ---------------- K4: node post ----------------
// 16 nodes per block, 256 threads, dynamic smem
#define K4_SMEM_FLOATS (16 * 1024 + 16 * 128 + 16 * 384 + 16 * 256 + 16 * 384)
__global__ void k_node_post(const float* __restrict__ W1s, const float* __restrict__ W1v,
                            const float* __restrict__ Wrs, const float* __restrict__ Wrv,
                            const float* __restrict__ W2s, const float* __restrict__ W2v,
                            const float* __restrict__ alpha, const float* __restrict__ beta,
                            float* __restrict__ out) {
    extern __shared__ float sm[];
    float* s_msg = sm;                 // 16*1024  (u*4 + comp)
    float* s_us  = s_msg + 16 * 1024;  // 16*128
    float* s_uv  = s_us + 16 * 128;    // 16*384
    float* s_ms  = s_uv + 16 * 384;    // 16*256
    float* s_mv  = s_ms + 16 * 256;    // 16*384
    __shared__ float s_invden[16];

    int nb = blockIdx.x * 16;
    int tid = threadIdx.x;
    const float* gmsg = (const float*)g_msg4;

    for (int idx = tid; idx < 16 * 1024; idx += 256) s_msg[idx] = gmsg[(size_t)nb * 1024 + idx];
    for (int idx = tid; idx < 16 * 128; idx += 256)  s_us[idx] = g_us[nb * 128 + idx];
    for (int idx = tid; idx < 16 * 384; idx += 256)  s_uv[idx] = g_uv[nb * 384 + idx];
    if (tid < 16) s_invden[tid] = 1.0f / (g_density[nb + tid] * (*beta) + (*alpha));
    __syncthreads();

    const float s16 = 0.0625f;
    // m_s: 16*256 items
    for (int it = tid; it < 4096; it += 256) {
        int nn = it >> 8, w = it & 255;
        float a = 0.f;
        #pragma unroll 4
        for (int u = 0; u < 256; u++) a += s_msg[nn * 1024 + u * 4] * W1s[u * 256 + w];
        float b = 0.f;
        #pragma unroll 4
        for (int u = 0; u < 128; u++) b += s_us[nn * 128 + u] * Wrs[u * 256 + w];
        s_ms[nn * 256 + w] = a * s16 * s_invden[nn] + b * R128;
    }
    // m_v: 16*128*3 items
    for (int it = tid; it < 6144; it += 256) {
        int nn = it / 384; int r = it - nn * 384;
        int w = r / 3, c = r - 3 * w;
        float a = 0.f;
        #pragma unroll 4
        for (int u = 0; u < 256; u++) a += s_msg[nn * 1024 + u * 4 + 1 + c] * W1v[u * 128 + w];
        float b = 0.f;
        #pragma unroll 4
        for (int u = 0; u < 128; u++) b += s_uv[nn * 384 + u * 3 + c] * Wrv[u * 128 + w];
        s_mv[nn * 384 + r] = a * s16 * s_invden[nn] + b * R128;
    }
    __syncthreads();

    // gate: out_s = silu(m_s[:128]); out_v = m_v * sigmoid(m_s[128:])
    for (int it = tid; it < 2048; it += 256) {
        int nn = it >> 7, u = it & 127;
        float x = s_ms[nn * 256 + u];
        s_ms[nn * 256 + u] = silu_f(x);
        float g = 1.f / (1.f + __expf(-s_ms[nn * 256 + 128 + u]));
        s_mv[nn * 384 + u * 3 + 0] *= g;
        s_mv[nn * 384 + u * 3 + 1] *= g;
        s_mv[nn * 384 + u * 3 + 2] *= g;
    }
    __syncthreads();

    // f_s -> out[n][w][0]
    for (int it = tid; it < 2048; it += 256) {
        int nn = it >> 7, w = it & 127;
        float a = 0.f;
        #pragma unroll 4
        for (int u = 0; u < 128; u++) a += s_ms[nn * 256 + u] * W2s[u * 128 + w];
        out[(size_t)(nb + nn) * 512 + w * 4] = a * R128;
    }
    // f_v -> out[n][w][1+c]
    for (int it = tid; it < 6144; it += 256) {
        int nn = it / 384; int r = it - nn * 384;
        int w = r / 3, c = r - 3 * w;
        float a = 0.f;
        #pragma unroll 4
        for (int u = 0; u < 128; u++) a += s_mv[nn * 384 + u * 3 + c] * W2v[u * 128 + w];
        out[(size_t)(nb + nn) * 512 + w * 4 + 1 + c] = a * R128;
    }
}

// ---------------- launch ----------------
extern "C" void kernel_launch(void* const* d_in, const int* in_sizes, int n_in,
                              void* d_out, int out_size) {
    const float* node_attrs = (const float*)d_in[0];
    const float* node_feats = (const float*)d_in[1];
    const float* edge_attrs = (const float*)d_in[2];
    const float* edge_feats = (const float*)d_in[3];
    const int*   edge_index = (const int*)d_in[4];
    const float* W_skip_s = (const float*)d_in[5];
    const float* W_skip_v = (const float*)d_in[6];
    const float* W_up_s   = (const float*)d_in[7];
    const float* W_up_v   = (const float*)d_in[8];
    const float* W_src    = (const float*)d_in[9];
    const float* W_tgt    = (const float*)d_in[10];
    const float* W_r0     = (const float*)d_in[11];
    const float* W_r1     = (const float*)d_in[12];
    const float* W_r2     = (const float*)d_in[13];
    const float* W_r3     = (const float*)d_in[14];
    const float* W_d0     = (const float*)d_in[15];
    const float* W_d1     = (const float*)d_in[16];
    const float* W1_s     = (const float*)d_in[17];
    const float* W1_v     = (const float*)d_in[18];
    const float* Wres_s   = (const float*)d_in[19];
    const float* Wres_v   = (const float*)d_in[20];
    const float* W2_s     = (const float*)d_in[21];
    const float* W2_v     = (const float*)d_in[22];
    const float* alpha    = (const float*)d_in[23];
    const float* beta     = (const float*)d_in[24];

    float* out = (float*)d_out;                      // (N,128,4) flattened
    float* out_sc = out + (size_t)NN * 512;          // (N,512)

    size_t smem_k2 = (size_t)K2_SMEM_FLOATS * sizeof(float);
    size_t smem_k4 = (size_t)K4_SMEM_FLOATS * sizeof(float);
    cudaFuncSetAttribute(k_edge_mlp, cudaFuncAttributeMaxDynamicSharedMemorySize, (int)smem_k2);
    cudaFuncSetAttribute(k_node_post, cudaFuncAttributeMaxDynamicSharedMemorySize, (int)smem_k4);

    k_zero<<<(NN * 256 + 255) / 256, 256>>>();
    k_node_pre<<<NN / 16, 256>>>(node_attrs, node_feats, W_skip_s, W_skip_v,
                                 W_up_s, W_up_v, W_src, W_tgt, out_sc);
    k_edge_mlp<<<EE / 64, 256, smem_k2>>>(edge_feats, edge_index,
                                          W_r0, W_r1, W_r2, W_r3, W_d0, W_d1);
    k_message<<<EE / 8, 256>>>(edge_attrs, edge_index);
    k_node_post<<<NN / 16, 256, smem_k4>>>(W1_s, W1_v, Wres_s, Wres_v, W2_s, W2_v,
                                           alpha, beta, out);
}

// round 4
// speedup vs baseline: 1.0769x; 1.0769x over previous
#include <cuda_runtime.h>
#include <cstdint>

#define NN 8192
#define EE 131072
#define MUL 128

#define R128 0.08838834764831845f
#define R10  0.31622776601683794f
#define RS264 0.06154574548966637f
#define INV3 0.5773502691896258f

typedef unsigned long long u64;

// ---------------- scratch (device globals; no allocation allowed) ----------------
__device__ float  g_us[NN * 128];        // up-scalar
__device__ float  g_uv[NN * 384];        // up-vector [n][u][c]
__device__ float  g_src[NN * 128];
__device__ float  g_tgt[NN * 128];
__device__ float4 g_msg4[NN * 256];      // [n][u] = (s, v0, v1, v2)
__device__ float  g_density[NN];

__device__ __forceinline__ float silu_f(float x) {
    return x / (1.0f + __expf(-x));
}

__device__ __forceinline__ void red4(float4* p, float a, float b, float c, float d) {
    asm volatile("red.global.add.v4.f32 [%0], {%1,%2,%3,%4};"
                 :: "l"(p), "f"(a), "f"(b), "f"(c), "f"(d) : "memory");
}

// ---- packed f32x2 helpers ----
__device__ __forceinline__ u64 pack2(float lo, float hi) {
    u64 r; asm("mov.b64 %0, {%1, %2};" : "=l"(r) : "f"(lo), "f"(hi)); return r;
}
__device__ __forceinline__ float2 unpack2(u64 v) {
    float2 r; asm("mov.b64 {%0, %1}, %2;" : "=f"(r.x), "=f"(r.y) : "l"(v)); return r;
}
__device__ __forceinline__ u64 fma2(u64 a, u64 b, u64 c) {
    u64 d; asm("fma.rn.f32x2 %0, %1, %2, %3;" : "=l"(d) : "l"(a), "l"(b), "l"(c)); return d;
}

// ---------------- K0: zero accumulators ----------------
__global__ void k_zero() {
    int i = blockIdx.x * blockDim.x + threadIdx.x;
    if (i < NN * 256) g_msg4[i] = make_float4(0.f, 0.f, 0.f, 0.f);
    if (i < NN) g_density[i] = 0.f;
}

// ---------------- K1: node pre (us, uv, src_e, tgt_e, sc) ----------------
__global__ void k_node_pre(const float* __restrict__ na, const float* __restrict__ nf,
                           const float* __restrict__ Wss, const float* __restrict__ Wsv,
                           const float* __restrict__ Wus, const float* __restrict__ Wuv,
                           const float* __restrict__ Wsrc, const float* __restrict__ Wtgt,
                           float* __restrict__ out_sc) {
    __shared__ float s_s[16][128];
    __shared__ float s_v[16][384];
    __shared__ float s_a[16][10];
    int nb = blockIdx.x * 16;
    int tid = threadIdx.x;

    for (int idx = tid; idx < 16 * 512; idx += 256) {
        int nn = idx >> 9, j = idx & 511;
        float val = nf[(nb + nn) * 512 + j];
        if (j < 128) s_s[nn][j] = val;
        else         s_v[nn][j - 128] = val;
    }
    for (int idx = tid; idx < 160; idx += 256) {
        int nn = idx / 10, j = idx - nn * 10;
        s_a[nn][j] = na[(nb + nn) * 10 + j];
    }
    __syncthreads();

    for (int it = tid; it < 2048; it += 256) {
        int nn = it >> 7, w = it & 127;
        float a_up = 0.f, a_sk = 0.f, a_src = 0.f, a_tgt = 0.f;
        #pragma unroll 4
        for (int u = 0; u < 128; u++) {
            float x = s_s[nn][u];
            a_up += x * Wus[u * 128 + w];
            a_sk += x * Wss[u * 128 + w];
        }
        #pragma unroll
        for (int u = 0; u < 10; u++) {
            float x = s_a[nn][u];
            a_src += x * Wsrc[u * 128 + w];
            a_tgt += x * Wtgt[u * 128 + w];
        }
        int n = nb + nn;
        g_us[n * 128 + w]  = a_up * R128;
        g_src[n * 128 + w] = a_src * R10;
        g_tgt[n * 128 + w] = a_tgt * R10;
        out_sc[(size_t)n * 512 + w] = a_sk * R128;
    }
    for (int it = tid; it < 6144; it += 256) {
        int nn = it / 384; int r = it - nn * 384;
        int w = r / 3, c = r - 3 * w;
        float a_up = 0.f, a_sk = 0.f;
        #pragma unroll 4
        for (int u = 0; u < 128; u++) {
            float x = s_v[nn][u * 3 + c];
            a_up += x * Wuv[u * 128 + w];
            a_sk += x * Wsv[u * 128 + w];
        }
        int n = nb + nn;
        g_uv[n * 384 + r] = a_up * R128;
        out_sc[(size_t)n * 512 + 128 + r] = a_sk * R128;
    }
}

// ---------------- K2: fused edge MLP + message scatter ----------------
// 64 edges/block, 256 threads. f32x2 packed math, K-major activations,
// duplicated weights in smem, fused red4 epilogue (no g_tpw round-trip).

#define EFT_STRIDE 68
#define TPW_STRIDE 66
#define EFT_BYTES  (264 * EFT_STRIDE * 4)          // 71808 (>= 256*66*4 = 67584 for tpwT)
#define WD_OFF     EFT_BYTES
#define WD_BYTES   (88 * 64 * 8)                   // 45056
#define HAT_OFF    (WD_OFF + WD_BYTES)
#define HBT_OFF    (HAT_OFF + 64 * 64 * 4)
#define SY_OFF     (HBT_OFF + 64 * 64 * 4)
#define SND_OFF    (SY_OFF + 64 * 4 * 4)
#define RCV_OFF    (SND_OFF + 64 * 4)
#define K2_SMEM    (RCV_OFF + 64 * 4)              // 151168 bytes

// stage W (row-major, row stride ldw, col offset c0, krows rows of 64 cols)
// into smem as duplicated {w,w} u64 entries.
__device__ __forceinline__ void stageW_dup(u64* Wd, const float* __restrict__ W,
                                           int ldw, int c0, int krows, int tid) {
    for (int idx = tid; idx < krows * 32; idx += 256) {
        int k = idx >> 5, j = (idx & 31) * 2;
        float2 w = *(const float2*)(W + (size_t)k * ldw + c0 + j);
        Wd[k * 64 + j]     = pack2(w.x, w.x);
        Wd[k * 64 + j + 1] = pack2(w.y, w.y);
    }
}

template<int K>
__device__ __forceinline__ void gemm_f32x2(const float* __restrict__ XT, int xstride,
                                           const u64* __restrict__ Wd,
                                           int t2, int o0, u64* acc) {
    #pragma unroll 4
    for (int k = 0; k < K; k++) {
        u64 xA = *(const u64*)(XT + k * xstride + t2);
        u64 xB = *(const u64*)(XT + k * xstride + 32 + t2);
        const u64* wr = Wd + k * 64 + o0;
        ulonglong2 wa = *(const ulonglong2*)wr;
        ulonglong2 wb = *(const ulonglong2*)(wr + 2);
        acc[0] = fma2(xA, wa.x, acc[0]);
        acc[1] = fma2(xA, wa.y, acc[1]);
        acc[2] = fma2(xA, wb.x, acc[2]);
        acc[3] = fma2(xA, wb.y, acc[3]);
        acc[4] = fma2(xB, wa.x, acc[4]);
        acc[5] = fma2(xB, wa.y, acc[5]);
        acc[6] = fma2(xB, wb.x, acc[6]);
        acc[7] = fma2(xB, wb.y, acc[7]);
    }
}

__device__ __forceinline__ void zero8(u64* acc) {
    #pragma unroll
    for (int i = 0; i < 8; i++) acc[i] = 0ull;
}

__device__ __forceinline__ void write_act(float* dst, int t2, int o0, const u64* acc,
                                          float scale, bool act) {
    #pragma unroll
    for (int o = 0; o < 4; o++) {
        float2 a = unpack2(acc[o]);
        float2 b = unpack2(acc[4 + o]);
        a.x *= scale; a.y *= scale; b.x *= scale; b.y *= scale;
        if (act) { a.x = silu_f(a.x); a.y = silu_f(a.y); b.x = silu_f(b.x); b.y = silu_f(b.y); }
        *(u64*)(dst + (o0 + o) * 64 + t2)      = pack2(a.x, a.y);
        *(u64*)(dst + (o0 + o) * 64 + 32 + t2) = pack2(b.x, b.y);
    }
}

__global__ __launch_bounds__(256, 1)
void k_edge_fused(const float* __restrict__ ef_in, const int* __restrict__ ei,
                  const float* __restrict__ ea,
                  const float* __restrict__ Wr0, const float* __restrict__ Wr1,
                  const float* __restrict__ Wr2, const float* __restrict__ Wr3,
                  const float* __restrict__ Wd0, const float* __restrict__ Wd1) {
    extern __shared__ char smraw[];
    float* efT  = (float*)smraw;                 // [264][EFT_STRIDE], K-major
    float* tpwT = (float*)smraw;                 // reuse: [256][TPW_STRIDE]
    u64*   Wd   = (u64*)(smraw + WD_OFF);        // [<=88][64] duplicated
    float* HaT  = (float*)(smraw + HAT_OFF);     // [64][64]
    float* HbT  = (float*)(smraw + HBT_OFF);     // [64][64]
    float* sy   = (float*)(smraw + SY_OFF);      // [64][4]
    int*   ssnd = (int*)(smraw + SND_OFF);
    int*   srcv = (int*)(smraw + RCV_OFF);

    int eb = blockIdx.x * 64;
    int tid = threadIdx.x;
    int t2 = (tid & 15) * 2;        // edge pair base within half (edges t2,t2+1 and 32+t2,33+t2)
    int o0 = (tid >> 4) * 4;        // 4 output columns

    if (tid < 64) { ssnd[tid] = ei[eb + tid]; srcv[tid] = ei[EE + eb + tid]; }
    sy[tid & 255] = ea[(size_t)eb * 4 + tid];   // 256 values = 64 edges x 4
    __syncthreads();

    // ---- stage efT (K-major): rows 0..7 edge_feats, 8..135 src_e[snd], 136..263 tgt_e[rcv]
    for (int idx = tid; idx < 512; idx += 256) {
        int e = idx >> 3, i = idx & 7;
        efT[i * EFT_STRIDE + e] = ef_in[(size_t)(eb + e) * 8 + i];
    }
    for (int idx = tid; idx < 2048; idx += 256) {
        int e = idx >> 5, j = (idx & 31) * 4;
        float4 v = *(const float4*)(g_src + (size_t)ssnd[e] * 128 + j);
        efT[(8 + j + 0) * EFT_STRIDE + e] = v.x;
        efT[(8 + j + 1) * EFT_STRIDE + e] = v.y;
        efT[(8 + j + 2) * EFT_STRIDE + e] = v.z;
        efT[(8 + j + 3) * EFT_STRIDE + e] = v.w;
    }
    for (int idx = tid; idx < 2048; idx += 256) {
        int e = idx >> 5, j = (idx & 31) * 4;
        float4 v = *(const float4*)(g_tgt + (size_t)srcv[e] * 128 + j);
        efT[(136 + j + 0) * EFT_STRIDE + e] = v.x;
        efT[(136 + j + 1) * EFT_STRIDE + e] = v.y;
        efT[(136 + j + 2) * EFT_STRIDE + e] = v.z;
        efT[(136 + j + 3) * EFT_STRIDE + e] = v.w;
    }
    __syncthreads();

    u64 acc[8];

    // ---- layer 0, r-path: efT(264) @ Wr0 -> HaT (silu)
    zero8(acc);
    for (int c = 0; c < 3; c++) {
        stageW_dup(Wd, Wr0 + (size_t)c * 88 * 64, 64, 0, 88, tid);
        __syncthreads();
        gemm_f32x2<88>(efT + c * 88 * EFT_STRIDE, EFT_STRIDE, Wd, t2, o0, acc);
        __syncthreads();
    }
    write_act(HaT, t2, o0, acc, RS264, true);

    // ---- layer 0, d-path: efT(264) @ Wd0 -> HbT (silu)
    zero8(acc);
    for (int c = 0; c < 3; c++) {
        stageW_dup(Wd, Wd0 + (size_t)c * 88 * 64, 64, 0, 88, tid);
        __syncthreads();
        gemm_f32x2<88>(efT + c * 88 * EFT_STRIDE, EFT_STRIDE, Wd, t2, o0, acc);
        __syncthreads();
    }
    write_act(HbT, t2, o0, acc, RS264, true);
    __syncthreads();   // HbT complete before density reads

    // ---- density head + stage Wr1
    if (tid < 64) {
        float a = 0.f;
        #pragma unroll 8
        for (int o = 0; o < 64; o++) a += HbT[o * 64 + tid] * Wd1[o];
        a *= 0.125f;
        atomicAdd(&g_density[srcv[tid]], tanhf(a * a));
    }
    stageW_dup(Wd, Wr1, 64, 0, 64, tid);
    __syncthreads();   // density done (HbT free) + Wr1 staged

    // ---- layer 1: HaT @ Wr1 -> HbT (silu)
    zero8(acc);
    gemm_f32x2<64>(HaT, 64, Wd, t2, o0, acc);
    write_act(HbT, t2, o0, acc, 0.125f, true);
    __syncthreads();

    // ---- layer 2: HbT @ Wr2 -> HaT (silu)
    stageW_dup(Wd, Wr2, 64, 0, 64, tid);
    __syncthreads();
    zero8(acc);
    gemm_f32x2<64>(HbT, 64, Wd, t2, o0, acc);
    write_act(HaT, t2, o0, acc, 0.125f, true);
    __syncthreads();

    // ---- layer 3 (8 passes of 64 cols) + fused message epilogues
    for (int p = 0; p < 8; p++) {
        stageW_dup(Wd, Wr3, 512, p * 64, 64, tid);
        __syncthreads();
        zero8(acc);
        gemm_f32x2<64>(HaT, 64, Wd, t2, o0, acc);
        int rp = (p & 3) * 64 + o0;
        #pragma unroll
        for (int o = 0; o < 4; o++) {
            float2 a = unpack2(acc[o]);
            float2 b = unpack2(acc[4 + o]);
            *(u64*)(tpwT + (rp + o) * TPW_STRIDE + t2)      = pack2(a.x * 0.125f, a.y * 0.125f);
            *(u64*)(tpwT + (rp + o) * TPW_STRIDE + 32 + t2) = pack2(b.x * 0.125f, b.y * 0.125f);
        }
        __syncthreads();

        if (p == 3) {
            // epilogue A: cols 0..255 => w1, w2  (scalar msg + m1a vector part)
            for (int it = tid; it < 8192; it += 256) {
                int e = it >> 7, u = it & 127;
                float w1 = tpwT[u * TPW_STRIDE + e];
                float w2 = tpwT[(128 + u) * TPW_STRIDE + e];
                float xs = g_us[(size_t)ssnd[e] * 128 + u];
                float y0  = sy[e * 4 + 0];
                float y1x = sy[e * 4 + 1];
                float y1y = sy[e * 4 + 2];
                float y1z = sy[e * 4 + 3];
                float a  = w1 * xs * y0;
                float sx = w2 * xs * INV3;
                red4(g_msg4 + (size_t)srcv[e] * 256 + u, a, sx * y1x, sx * y1y, sx * y1z);
            }
            __syncthreads();
        }
    }
    // epilogue B: cols 256..511 => w3, w4  (m0b scalar + m1b vector part)
    for (int it = tid; it < 8192; it += 256) {
        int e = it >> 7, u = it & 127;
        float w3 = tpwT[u * TPW_STRIDE + e];
        float w4 = tpwT[(128 + u) * TPW_STRIDE + e];
        const float* xvp = g_uv + (size_t)ssnd[e] * 384 + u * 3;
        float vx = xvp[0], vy = xvp[1], vz = xvp[2];
        float y0  = sy[e * 4 + 0];
        float y1x = sy[e * 4 + 1];
        float y1y = sy[e * 4 + 2];
        float y1z = sy[e * 4 + 3];
        float dot = vx * y1x + vy * y1y + vz * y1z;
        float a2 = w4 * dot * INV3;
        float s3 = w3 * y0 * INV3;
        red4(g_msg4 + (size_t)srcv[e] * 256 + 128 + u, a2, s3 * vx, s3 * vy, s3 * vz);
    }
}

// ---------------- K4: node post ----------------
#define K4_SMEM_FLOATS (16 * 1024 + 16 * 128 + 16 * 384 + 16 * 256 + 16 * 384)
__global__ void k_node_post(const float* __restrict__ W1s, const float* __restrict__ W1v,
                            const float* __restrict__ Wrs, const float* __restrict__ Wrv,
                            const float* __restrict__ W2s, const float* __restrict__ W2v,
                            const float* __restrict__ alpha, const float* __restrict__ beta,
                            float* __restrict__ out) {
    extern __shared__ float sm[];
    float* s_msg = sm;                 // 16*1024
    float* s_us  = s_msg + 16 * 1024;  // 16*128
    float* s_uv  = s_us + 16 * 128;    // 16*384
    float* s_ms  = s_uv + 16 * 384;    // 16*256
    float* s_mv  = s_ms + 16 * 256;    // 16*384
    __shared__ float s_invden[16];

    int nb = blockIdx.x * 16;
    int tid = threadIdx.x;
    const float* gmsg = (const float*)g_msg4;

    for (int idx = tid; idx < 16 * 1024; idx += 256) s_msg[idx] = gmsg[(size_t)nb * 1024 + idx];
    for (int idx = tid; idx < 16 * 128; idx += 256)  s_us[idx] = g_us[nb * 128 + idx];
    for (int idx = tid; idx < 16 * 384; idx += 256)  s_uv[idx] = g_uv[nb * 384 + idx];
    if (tid < 16) s_invden[tid] = 1.0f / (g_density[nb + tid] * (*beta) + (*alpha));
    __syncthreads();

    const float s16 = 0.0625f;
    for (int it = tid; it < 4096; it += 256) {
        int nn = it >> 8, w = it & 255;
        float a = 0.f;
        #pragma unroll 4
        for (int u = 0; u < 256; u++) a += s_msg[nn * 1024 + u * 4] * W1s[u * 256 + w];
        float b = 0.f;
        #pragma unroll 4
        for (int u = 0; u < 128; u++) b += s_us[nn * 128 + u] * Wrs[u * 256 + w];
        s_ms[nn * 256 + w] = a * s16 * s_invden[nn] + b * R128;
    }
    for (int it = tid; it < 6144; it += 256) {
        int nn = it / 384; int r = it - nn * 384;
        int w = r / 3, c = r - 3 * w;
        float a = 0.f;
        #pragma unroll 4
        for (int u = 0; u < 256; u++) a += s_msg[nn * 1024 + u * 4 + 1 + c] * W1v[u * 128 + w];
        float b = 0.f;
        #pragma unroll 4
        for (int u = 0; u < 128; u++) b += s_uv[nn * 384 + u * 3 + c] * Wrv[u * 128 + w];
        s_mv[nn * 384 + r] = a * s16 * s_invden[nn] + b * R128;
    }
    __syncthreads();

    for (int it = tid; it < 2048; it += 256) {
        int nn = it >> 7, u = it & 127;
        float x = s_ms[nn * 256 + u];
        s_ms[nn * 256 + u] = silu_f(x);
        float g = 1.f / (1.f + __expf(-s_ms[nn * 256 + 128 + u]));
        s_mv[nn * 384 + u * 3 + 0] *= g;
        s_mv[nn * 384 + u * 3 + 1] *= g;
        s_mv[nn * 384 + u * 3 + 2] *= g;
    }
    __syncthreads();

    for (int it = tid; it < 2048; it += 256) {
        int nn = it >> 7, w = it & 127;
        float a = 0.f;
        #pragma unroll 4
        for (int u = 0; u < 128; u++) a += s_ms[nn * 256 + u] * W2s[u * 128 + w];
        out[(size_t)(nb + nn) * 512 + w * 4] = a * R128;
    }
    for (int it = tid; it < 6144; it += 256) {
        int nn = it / 384; int r = it - nn * 384;
        int w = r / 3, c = r - 3 * w;
        float a = 0.f;
        #pragma unroll 4
        for (int u = 0; u < 128; u++) a += s_mv[nn * 384 + u * 3 + c] * W2v[u * 128 + w];
        out[(size_t)(nb + nn) * 512 + w * 4 + 1 + c] = a * R128;
    }
}

// ---------------- launch ----------------
extern "C" void kernel_launch(void* const* d_in, const int* in_sizes, int n_in,
                              void* d_out, int out_size) {
    const float* node_attrs = (const float*)d_in[0];
    const float* node_feats = (const float*)d_in[1];
    const float* edge_attrs = (const float*)d_in[2];
    const float* edge_feats = (const float*)d_in[3];
    const int*   edge_index = (const int*)d_in[4];
    const float* W_skip_s = (const float*)d_in[5];
    const float* W_skip_v = (const float*)d_in[6];
    const float* W_up_s   = (const float*)d_in[7];
    const float* W_up_v   = (const float*)d_in[8];
    const float* W_src    = (const float*)d_in[9];
    const float* W_tgt    = (const float*)d_in[10];
    const float* W_r0     = (const float*)d_in[11];
    const float* W_r1     = (const float*)d_in[12];
    const float* W_r2     = (const float*)d_in[13];
    const float* W_r3     = (const float*)d_in[14];
    const float* W_d0     = (const float*)d_in[15];
    const float* W_d1     = (const float*)d_in[16];
    const float* W1_s     = (const float*)d_in[17];
    const float* W1_v     = (const float*)d_in[18];
    const float* Wres_s   = (const float*)d_in[19];
    const float* Wres_v   = (const float*)d_in[20];
    const float* W2_s     = (const float*)d_in[21];
    const float* W2_v     = (const float*)d_in[22];
    const float* alpha    = (const float*)d_in[23];
    const float* beta     = (const float*)d_in[24];

    float* out = (float*)d_out;                      // (N,128,4) flattened
    float* out_sc = out + (size_t)NN * 512;          // (N,512)

    size_t smem_k4 = (size_t)K4_SMEM_FLOATS * sizeof(float);
    cudaFuncSetAttribute(k_edge_fused, cudaFuncAttributeMaxDynamicSharedMemorySize, K2_SMEM);
    cudaFuncSetAttribute(k_node_post, cudaFuncAttributeMaxDynamicSharedMemorySize, (int)smem_k4);

    k_zero<<<(NN * 256 + 255) / 256, 256>>>();
    k_node_pre<<<NN / 16, 256>>>(node_attrs, node_feats, W_skip_s, W_skip_v,
                                 W_up_s, W_up_v, W_src, W_tgt, out_sc);
    k_edge_fused<<<EE / 64, 256, K2_SMEM>>>(edge_feats, edge_index, edge_attrs,
                                            W_r0, W_r1, W_r2, W_r3, W_d0, W_d1);
    k_node_post<<<NN / 16, 256, smem_k4>>>(W1_s, W1_v, Wres_s, Wres_v, W2_s, W2_v,
                                           alpha, beta, out);
}

// round 5
// speedup vs baseline: 1.0788x; 1.0018x over previous
#include <cuda_runtime.h>
#include <cstdint>

#define NN 8192
#define EE 131072
#define MUL 128

#define R128 0.08838834764831845f
#define R10  0.31622776601683794f
#define RS264 0.06154574548966637f
#define INV3 0.5773502691896258f

typedef unsigned long long u64;

// ---------------- scratch (device globals; no allocation allowed) ----------------
__device__ float  g_us[NN * 128];        // up-scalar
__device__ float  g_uv[NN * 384];        // up-vector [n][u][c]
__device__ float  g_src[NN * 128];
__device__ float  g_tgt[NN * 128];
__device__ float4 g_msg4[NN * 256];      // [n][u] = (s, v0, v1, v2)
__device__ float  g_density[NN];

__device__ __forceinline__ float silu_f(float x) {
    return x / (1.0f + __expf(-x));
}

__device__ __forceinline__ void red4(float4* p, float a, float b, float c, float d) {
    asm volatile("red.global.add.v4.f32 [%0], {%1,%2,%3,%4};"
                 :: "l"(p), "f"(a), "f"(b), "f"(c), "f"(d) : "memory");
}

// ---- packed f32x2 helpers ----
__device__ __forceinline__ u64 pack2(float lo, float hi) {
    u64 r; asm("mov.b64 %0, {%1, %2};" : "=l"(r) : "f"(lo), "f"(hi)); return r;
}
__device__ __forceinline__ float2 unpack2(u64 v) {
    float2 r; asm("mov.b64 {%0, %1}, %2;" : "=f"(r.x), "=f"(r.y) : "l"(v)); return r;
}
__device__ __forceinline__ u64 fma2(u64 a, u64 b, u64 c) {
    u64 d; asm("fma.rn.f32x2 %0, %1, %2, %3;" : "=l"(d) : "l"(a), "l"(b), "l"(c)); return d;
}

// ---------------- K0: zero accumulators ----------------
__global__ void k_zero() {
    int i = blockIdx.x * blockDim.x + threadIdx.x;
    if (i < NN * 256) g_msg4[i] = make_float4(0.f, 0.f, 0.f, 0.f);
    if (i < NN) g_density[i] = 0.f;
}

// ---------------- K1: node pre (us, uv, src_e, tgt_e, sc) ----------------
__global__ void k_node_pre(const float* __restrict__ na, const float* __restrict__ nf,
                           const float* __restrict__ Wss, const float* __restrict__ Wsv,
                           const float* __restrict__ Wus, const float* __restrict__ Wuv,
                           const float* __restrict__ Wsrc, const float* __restrict__ Wtgt,
                           float* __restrict__ out_sc) {
    __shared__ float s_s[16][128];
    __shared__ float s_v[16][384];
    __shared__ float s_a[16][10];
    int nb = blockIdx.x * 16;
    int tid = threadIdx.x;

    for (int idx = tid; idx < 16 * 512; idx += 256) {
        int nn = idx >> 9, j = idx & 511;
        float val = nf[(nb + nn) * 512 + j];
        if (j < 128) s_s[nn][j] = val;
        else         s_v[nn][j - 128] = val;
    }
    for (int idx = tid; idx < 160; idx += 256) {
        int nn = idx / 10, j = idx - nn * 10;
        s_a[nn][j] = na[(nb + nn) * 10 + j];
    }
    __syncthreads();

    for (int it = tid; it < 2048; it += 256) {
        int nn = it >> 7, w = it & 127;
        float a_up = 0.f, a_sk = 0.f, a_src = 0.f, a_tgt = 0.f;
        #pragma unroll 4
        for (int u = 0; u < 128; u++) {
            float x = s_s[nn][u];
            a_up += x * Wus[u * 128 + w];
            a_sk += x * Wss[u * 128 + w];
        }
        #pragma unroll
        for (int u = 0; u < 10; u++) {
            float x = s_a[nn][u];
            a_src += x * Wsrc[u * 128 + w];
            a_tgt += x * Wtgt[u * 128 + w];
        }
        int n = nb + nn;
        g_us[n * 128 + w]  = a_up * R128;
        g_src[n * 128 + w] = a_src * R10;
        g_tgt[n * 128 + w] = a_tgt * R10;
        out_sc[(size_t)n * 512 + w] = a_sk * R128;
    }
    for (int it = tid; it < 6144; it += 256) {
        int nn = it / 384; int r = it - nn * 384;
        int w = r / 3, c = r - 3 * w;
        float a_up = 0.f, a_sk = 0.f;
        #pragma unroll 4
        for (int u = 0; u < 128; u++) {
            float x = s_v[nn][u * 3 + c];
            a_up += x * Wuv[u * 128 + w];
            a_sk += x * Wsv[u * 128 + w];
        }
        int n = nb + nn;
        g_uv[n * 384 + r] = a_up * R128;
        out_sc[(size_t)n * 512 + 128 + r] = a_sk * R128;
    }
}

// ---------------- K2: fused edge MLP + message scatter ----------------
// 64 edges/block, 256 threads. f32x2 packed math, K-major activations,
// duplicated weights in smem, fused red4 epilogue (no g_tpw round-trip).

#define EFT_STRIDE 68
#define TPW_STRIDE 66
#define EFT_BYTES  (264 * EFT_STRIDE * 4)          // 71808 (>= 256*66*4 = 67584 for tpwT)
#define WD_OFF     EFT_BYTES
#define WD_BYTES   (88 * 64 * 8)                   // 45056
#define HAT_OFF    (WD_OFF + WD_BYTES)
#define HBT_OFF    (HAT_OFF + 64 * 64 * 4)
#define SY_OFF     (HBT_OFF + 64 * 64 * 4)
#define SND_OFF    (SY_OFF + 64 * 4 * 4)
#define RCV_OFF    (SND_OFF + 64 * 4)
#define K2_SMEM    (RCV_OFF + 64 * 4)              // 151168 bytes

// stage W (row-major, row stride ldw, col offset c0, krows rows of 64 cols)
// into smem as duplicated {w,w} u64 entries.
__device__ __forceinline__ void stageW_dup(u64* Wd, const float* __restrict__ W,
                                           int ldw, int c0, int krows, int tid) {
    for (int idx = tid; idx < krows * 32; idx += 256) {
        int k = idx >> 5, j = (idx & 31) * 2;
        float2 w = *(const float2*)(W + (size_t)k * ldw + c0 + j);
        Wd[k * 64 + j]     = pack2(w.x, w.x);
        Wd[k * 64 + j + 1] = pack2(w.y, w.y);
    }
}

template<int K>
__device__ __forceinline__ void gemm_f32x2(const float* __restrict__ XT, int xstride,
                                           const u64* __restrict__ Wd,
                                           int t2, int o0, u64* acc) {
    #pragma unroll 4
    for (int k = 0; k < K; k++) {
        u64 xA = *(const u64*)(XT + k * xstride + t2);
        u64 xB = *(const u64*)(XT + k * xstride + 32 + t2);
        const u64* wr = Wd + k * 64 + o0;
        ulonglong2 wa = *(const ulonglong2*)wr;
        ulonglong2 wb = *(const ulonglong2*)(wr + 2);
        acc[0] = fma2(xA, wa.x, acc[0]);
        acc[1] = fma2(xA, wa.y, acc[1]);
        acc[2] = fma2(xA, wb.x, acc[2]);
        acc[3] = fma2(xA, wb.y, acc[3]);
        acc[4] = fma2(xB, wa.x, acc[4]);
        acc[5] = fma2(xB, wa.y, acc[5]);
        acc[6] = fma2(xB, wb.x, acc[6]);
        acc[7] = fma2(xB, wb.y, acc[7]);
    }
}

__device__ __forceinline__ void zero8(u64* acc) {
    #pragma unroll
    for (int i = 0; i < 8; i++) acc[i] = 0ull;
}

__device__ __forceinline__ void write_act(float* dst, int t2, int o0, const u64* acc,
                                          float scale, bool act) {
    #pragma unroll
    for (int o = 0; o < 4; o++) {
        float2 a = unpack2(acc[o]);
        float2 b = unpack2(acc[4 + o]);
        a.x *= scale; a.y *= scale; b.x *= scale; b.y *= scale;
        if (act) { a.x = silu_f(a.x); a.y = silu_f(a.y); b.x = silu_f(b.x); b.y = silu_f(b.y); }
        *(u64*)(dst + (o0 + o) * 64 + t2)      = pack2(a.x, a.y);
        *(u64*)(dst + (o0 + o) * 64 + 32 + t2) = pack2(b.x, b.y);
    }
}

__global__ __launch_bounds__(256, 1)
void k_edge_fused(const float* __restrict__ ef_in, const int* __restrict__ ei,
                  const float* __restrict__ ea,
                  const float* __restrict__ Wr0, const float* __restrict__ Wr1,
                  const float* __restrict__ Wr2, const float* __restrict__ Wr3,
                  const float* __restrict__ Wd0, const float* __restrict__ Wd1) {
    extern __shared__ char smraw[];
    float* efT  = (float*)smraw;                 // [264][EFT_STRIDE], K-major
    float* tpwT = (float*)smraw;                 // reuse: [256][TPW_STRIDE]
    u64*   Wd   = (u64*)(smraw + WD_OFF);        // [<=88][64] duplicated
    float* HaT  = (float*)(smraw + HAT_OFF);     // [64][64]
    float* HbT  = (float*)(smraw + HBT_OFF);     // [64][64]
    float* sy   = (float*)(smraw + SY_OFF);      // [64][4]
    int*   ssnd = (int*)(smraw + SND_OFF);
    int*   srcv = (int*)(smraw + RCV_OFF);

    int eb = blockIdx.x * 64;
    int tid = threadIdx.x;
    int t2 = (tid & 15) * 2;        // edge pair base within half (edges t2,t2+1 and 32+t2,33+t2)
    int o0 = (tid >> 4) * 4;        // 4 output columns

    if (tid < 64) { ssnd[tid] = ei[eb + tid]; srcv[tid] = ei[EE + eb + tid]; }
    sy[tid & 255] = ea[(size_t)eb * 4 + tid];   // 256 values = 64 edges x 4
    __syncthreads();

    // ---- stage efT (K-major): rows 0..7 edge_feats, 8..135 src_e[snd], 136..263 tgt_e[rcv]
    for (int idx = tid; idx < 512; idx += 256) {
        int e = idx >> 3, i = idx & 7;
        efT[i * EFT_STRIDE + e] = ef_in[(size_t)(eb + e) * 8 + i];
    }
    for (int idx = tid; idx < 2048; idx += 256) {
        int e = idx >> 5, j = (idx & 31) * 4;
        float4 v = *(const float4*)(g_src + (size_t)ssnd[e] * 128 + j);
        efT[(8 + j + 0) * EFT_STRIDE + e] = v.x;
        efT[(8 + j + 1) * EFT_STRIDE + e] = v.y;
        efT[(8 + j + 2) * EFT_STRIDE + e] = v.z;
        efT[(8 + j + 3) * EFT_STRIDE + e] = v.w;
    }
    for (int idx = tid; idx < 2048; idx += 256) {
        int e = idx >> 5, j = (idx & 31) * 4;
        float4 v = *(const float4*)(g_tgt + (size_t)srcv[e] * 128 + j);
        efT[(136 + j + 0) * EFT_STRIDE + e] = v.x;
        efT[(136 + j + 1) * EFT_STRIDE + e] = v.y;
        efT[(136 + j + 2) * EFT_STRIDE + e] = v.z;
        efT[(136 + j + 3) * EFT_STRIDE + e] = v.w;
    }
    __syncthreads();

    u64 acc[8];

    // ---- layer 0, r-path: efT(264) @ Wr0 -> HaT (silu)
    zero8(acc);
    for (int c = 0; c < 3; c++) {
        stageW_dup(Wd, Wr0 + (size_t)c * 88 * 64, 64, 0, 88, tid);
        __syncthreads();
        gemm_f32x2<88>(efT + c * 88 * EFT_STRIDE, EFT_STRIDE, Wd, t2, o0, acc);
        __syncthreads();
    }
    write_act(HaT, t2, o0, acc, RS264, true);

    // ---- layer 0, d-path: efT(264) @ Wd0 -> HbT (silu)
    zero8(acc);
    for (int c = 0; c < 3; c++) {
        stageW_dup(Wd, Wd0 + (size_t)c * 88 * 64, 64, 0, 88, tid);
        __syncthreads();
        gemm_f32x2<88>(efT + c * 88 * EFT_STRIDE, EFT_STRIDE, Wd, t2, o0, acc);
        __syncthreads();
    }
    write_act(HbT, t2, o0, acc, RS264, true);
    __syncthreads();   // HbT complete before density reads

    // ---- density head + stage Wr1
    if (tid < 64) {
        float a = 0.f;
        #pragma unroll 8
        for (int o = 0; o < 64; o++) a += HbT[o * 64 + tid] * Wd1[o];
        a *= 0.125f;
        atomicAdd(&g_density[srcv[tid]], tanhf(a * a));
    }
    stageW_dup(Wd, Wr1, 64, 0, 64, tid);
    __syncthreads();   // density done (HbT free) + Wr1 staged

    // ---- layer 1: HaT @ Wr1 -> HbT (silu)
    zero8(acc);
    gemm_f32x2<64>(HaT, 64, Wd, t2, o0, acc);
    write_act(HbT, t2, o0, acc, 0.125f, true);
    __syncthreads();

    // ---- layer 2: HbT @ Wr2 -> HaT (silu)
    stageW_dup(Wd, Wr2, 64, 0, 64, tid);
    __syncthreads();
    zero8(acc);
    gemm_f32x2<64>(HbT, 64, Wd, t2, o0, acc);
    write_act(HaT, t2, o0, acc, 0.125f, true);
    __syncthreads();

    // ---- layer 3 (8 passes of 64 cols) + fused message epilogues
    for (int p = 0; p < 8; p++) {
        stageW_dup(Wd, Wr3, 512, p * 64, 64, tid);
        __syncthreads();
        zero8(acc);
        gemm_f32x2<64>(HaT, 64, Wd, t2, o0, acc);
        int rp = (p & 3) * 64 + o0;
        #pragma unroll
        for (int o = 0; o < 4; o++) {
            float2 a = unpack2(acc[o]);
            float2 b = unpack2(acc[4 + o]);
            *(u64*)(tpwT + (rp + o) * TPW_STRIDE + t2)      = pack2(a.x * 0.125f, a.y * 0.125f);
            *(u64*)(tpwT + (rp + o) * TPW_STRIDE + 32 + t2) = pack2(b.x * 0.125f, b.y * 0.125f);
        }
        __syncthreads();

        if (p == 3) {
            // epilogue A: cols 0..255 => w1, w2  (scalar msg + m1a vector part)
            for (int it = tid; it < 8192; it += 256) {
                int e = it >> 7, u = it & 127;
                float w1 = tpwT[u * TPW_STRIDE + e];
                float w2 = tpwT[(128 + u) * TPW_STRIDE + e];
                float xs = g_us[(size_t)ssnd[e] * 128 + u];
                float y0  = sy[e * 4 + 0];
                float y1x = sy[e * 4 + 1];
                float y1y = sy[e * 4 + 2];
                float y1z = sy[e * 4 + 3];
                float a  = w1 * xs * y0;
                float sx = w2 * xs * INV3;
                red4(g_msg4 + (size_t)srcv[e] * 256 + u, a, sx * y1x, sx * y1y, sx * y1z);
            }
            __syncthreads();
        }
    }
    // epilogue B: cols 256..511 => w3, w4  (m0b scalar + m1b vector part)
    for (int it = tid; it < 8192; it += 256) {
        int e = it >> 7, u = it & 127;
        float w3 = tpwT[u * TPW_STRIDE + e];
        float w4 = tpwT[(128 + u) * TPW_STRIDE + e];
        const float* xvp = g_uv + (size_t)ssnd[e] * 384 + u * 3;
        float vx = xvp[0], vy = xvp[1], vz = xvp[2];
        float y0  = sy[e * 4 + 0];
        float y1x = sy[e * 4 + 1];
        float y1y = sy[e * 4 + 2];
        float y1z = sy[e * 4 + 3];
        float dot = vx * y1x + vy * y1y + vz * y1z;
        float a2 = w4 * dot * INV3;
        float s3 = w3 * y0 * INV3;
        red4(g_msg4 + (size_t)srcv[e] * 256 + 128 + u, a2, s3 * vx, s3 * vy, s3 * vz);
    }
}

// ---------------- K4: node post ----------------
#define K4_SMEM_FLOATS (16 * 1024 + 16 * 128 + 16 * 384 + 16 * 256 + 16 * 384)
__global__ void k_node_post(const float* __restrict__ W1s, const float* __restrict__ W1v,
                            const float* __restrict__ Wrs, const float* __restrict__ Wrv,
                            const float* __restrict__ W2s, const float* __restrict__ W2v,
                            const float* __restrict__ alpha, const float* __restrict__ beta,
                            float* __restrict__ out) {
    extern __shared__ float sm[];
    float* s_msg = sm;                 // 16*1024
    float* s_us  = s_msg + 16 * 1024;  // 16*128
    float* s_uv  = s_us + 16 * 128;    // 16*384
    float* s_ms  = s_uv + 16 * 384;    // 16*256
    float* s_mv  = s_ms + 16 * 256;    // 16*384
    __shared__ float s_invden[16];

    int nb = blockIdx.x * 16;
    int tid = threadIdx.x;
    const float* gmsg = (const float*)g_msg4;

    for (int idx = tid; idx < 16 * 1024; idx += 256) s_msg[idx] = gmsg[(size_t)nb * 1024 + idx];
    for (int idx = tid; idx < 16 * 128; idx += 256)  s_us[idx] = g_us[nb * 128 + idx];
    for (int idx = tid; idx < 16 * 384; idx += 256)  s_uv[idx] = g_uv[nb * 384 + idx];
    if (tid < 16) s_invden[tid] = 1.0f / (g_density[nb + tid] * (*beta) + (*alpha));
    __syncthreads();

    const float s16 = 0.0625f;
    for (int it = tid; it < 4096; it += 256) {
        int nn = it >> 8, w = it & 255;
        float a = 0.f;
        #pragma unroll 4
        for (int u = 0; u < 256; u++) a += s_msg[nn * 1024 + u * 4] * W1s[u * 256 + w];
        float b = 0.f;
        #pragma unroll 4
        for (int u = 0; u < 128; u++) b += s_us[nn * 128 + u] * Wrs[u * 256 + w];
        s_ms[nn * 256 + w] = a * s16 * s_invden[nn] + b * R128;
    }
    for (int it = tid; it < 6144; it += 256) {
        int nn = it / 384; int r = it - nn * 384;
        int w = r / 3, c = r - 3 * w;
        float a = 0.f;
        #pragma unroll 4
        for (int u = 0; u < 256; u++) a += s_msg[nn * 1024 + u * 4 + 1 + c] * W1v[u * 128 + w];
        float b = 0.f;
        #pragma unroll 4
        for (int u = 0; u < 128; u++) b += s_uv[nn * 384 + u * 3 + c] * Wrv[u * 128 + w];
        s_mv[nn * 384 + r] = a * s16 * s_invden[nn] + b * R128;
    }
    __syncthreads();

    for (int it = tid; it < 2048; it += 256) {
        int nn = it >> 7, u = it & 127;
        float x = s_ms[nn * 256 + u];
        s_ms[nn * 256 + u] = silu_f(x);
        float g = 1.f / (1.f + __expf(-s_ms[nn * 256 + 128 + u]));
        s_mv[nn * 384 + u * 3 + 0] *= g;
        s_mv[nn * 384 + u * 3 + 1] *= g;
        s_mv[nn * 384 + u * 3 + 2] *= g;
    }
    __syncthreads();

    for (int it = tid; it < 2048; it += 256) {
        int nn = it >> 7, w = it & 127;
        float a = 0.f;
        #pragma unroll 4
        for (int u = 0; u < 128; u++) a += s_ms[nn * 256 + u] * W2s[u * 128 + w];
        out[(size_t)(nb + nn) * 512 + w * 4] = a * R128;
    }
    for (int it = tid; it < 6144; it += 256) {
        int nn = it / 384; int r = it - nn * 384;
        int w = r / 3, c = r - 3 * w;
        float a = 0.f;
        #pragma unroll 4
        for (int u = 0; u < 128; u++) a += s_mv[nn * 384 + u * 3 + c] * W2v[u * 128 + w];
        out[(size_t)(nb + nn) * 512 + w * 4 + 1 + c] = a * R128;
    }
}

// ---------------- launch ----------------
extern "C" void kernel_launch(void* const* d_in, const int* in_sizes, int n_in,
                              void* d_out, int out_size) {
    const float* node_attrs = (const float*)d_in[0];
    const float* node_feats = (const float*)d_in[1];
    const float* edge_attrs = (const float*)d_in[2];
    const float* edge_feats = (const float*)d_in[3];
    const int*   edge_index = (const int*)d_in[4];
    const float* W_skip_s = (const float*)d_in[5];
    const float* W_skip_v = (const float*)d_in[6];
    const float* W_up_s   = (const float*)d_in[7];
    const float* W_up_v   = (const float*)d_in[8];
    const float* W_src    = (const float*)d_in[9];
    const float* W_tgt    = (const float*)d_in[10];
    const float* W_r0     = (const float*)d_in[11];
    const float* W_r1     = (const float*)d_in[12];
    const float* W_r2     = (const float*)d_in[13];
    const float* W_r3     = (const float*)d_in[14];
    const float* W_d0     = (const float*)d_in[15];
    const float* W_d1     = (const float*)d_in[16];
    const float* W1_s     = (const float*)d_in[17];
    const float* W1_v     = (const float*)d_in[18];
    const float* Wres_s   = (const float*)d_in[19];
    const float* Wres_v   = (const float*)d_in[20];
    const float* W2_s     = (const float*)d_in[21];
    const float* W2_v     = (const float*)d_in[22];
    const float* alpha    = (const float*)d_in[23];
    const float* beta     = (const float*)d_in[24];

    float* out = (float*)d_out;                      // (N,128,4) flattened
    float* out_sc = out + (size_t)NN * 512;          // (N,512)

    size_t smem_k4 = (size_t)K4_SMEM_FLOATS * sizeof(float);
    cudaFuncSetAttribute(k_edge_fused, cudaFuncAttributeMaxDynamicSharedMemorySize, K2_SMEM);
    cudaFuncSetAttribute(k_node_post, cudaFuncAttributeMaxDynamicSharedMemorySize, (int)smem_k4);

    k_zero<<<(NN * 256 + 255) / 256, 256>>>();
    k_node_pre<<<NN / 16, 256>>>(node_attrs, node_feats, W_skip_s, W_skip_v,
                                 W_up_s, W_up_v, W_src, W_tgt, out_sc);
    k_edge_fused<<<EE / 64, 256, K2_SMEM>>>(edge_feats, edge_index, edge_attrs,
                                            W_r0, W_r1, W_r2, W_r3, W_d0, W_d1);
    k_node_post<<<NN / 16, 256, smem_k4>>>(W1_s, W1_v, Wres_s, Wres_v, W2_s, W2_v,
                                           alpha, beta, out);
}